// round 10
// baseline (speedup 1.0000x reference)
#include <cuda_runtime.h>
#include <cuda_bf16.h>
#include <cstdint>

#define BATCH  8
#define LTOK   4096
#define DIMC   384
#define DIN    768
#define DSTATE 64
#define DTRANK 24
#define HIDC   1536
#define MROWS  (BATCH*LTOK)   // 32768
#define XDBP   192            // padded xproj width (152 -> 192)

typedef __nv_bfloat16 bf16;

// ---------------- scratch (static device memory) ---------------------------
__device__ float g_xz [ (size_t)MROWS*1536 ];
__device__ float g_xc [ (size_t)MROWS*DIN  ];
__device__ float g_xdb[ (size_t)MROWS*XDBP ];
__device__ float g_x2 [ (size_t)MROWS*DIMC ];
__device__ float g_f1 [ (size_t)MROWS*HIDC ];

__device__ alignas(16) bf16 g_xnh[ (size_t)MROWS*DIMC ];
__device__ alignas(16) bf16 g_xnl[ (size_t)MROWS*DIMC ];
__device__ alignas(16) bf16 g_xch[ (size_t)MROWS*DIN  ];
__device__ alignas(16) bf16 g_xcl[ (size_t)MROWS*DIN  ];
__device__ alignas(16) bf16 g_yh [ (size_t)MROWS*DIN  ];
__device__ alignas(16) bf16 g_yl [ (size_t)MROWS*DIN  ];
__device__ alignas(16) bf16 g_f2h[ (size_t)MROWS*HIDC ];
__device__ alignas(16) bf16 g_f2l[ (size_t)MROWS*HIDC ];

// weights hi/lo
__device__ alignas(16) bf16 g_winh[1536*384], g_winl[1536*384];
__device__ alignas(16) bf16 g_wxh [XDBP*768], g_wxl [XDBP*768];
__device__ alignas(16) bf16 g_woh [384*768],  g_wol [384*768];
__device__ alignas(16) bf16 g_w1h [1536*384], g_w1l [1536*384];
__device__ alignas(16) bf16 g_w2h [384*1536], g_w2l [384*1536];

__device__ __forceinline__ void split_bf16(float v, bf16& h, bf16& l) {
    h = __float2bfloat16(v);
    l = __float2bfloat16(v - __bfloat162float(h));
}

// ---------------- ALL dense weight conversions in ONE launch ----------------
// segments: W_in[589824] | W_out[294912] | W1[589824] | W2[589824]
#define WSEG0 589824
#define WSEG1 (WSEG0 + 294912)   // 884736
#define WSEG2 (WSEG1 + 589824)   // 1474560
#define WTOT  (WSEG2 + 589824)   // 2064384
__global__ void wconv_all_kernel(const float* __restrict__ Win,  bf16* winh, bf16* winl,
                                 const float* __restrict__ Wout, bf16* woh,  bf16* wol,
                                 const float* __restrict__ W1,   bf16* w1h,  bf16* w1l,
                                 const float* __restrict__ W2,   bf16* w2h,  bf16* w2l) {
    int i = blockIdx.x * 256 + threadIdx.x;
    if (i >= WTOT) return;
    const float* src; bf16 *dh, *dl; int j;
    if (i < WSEG0)      { src = Win;  dh = winh; dl = winl; j = i; }
    else if (i < WSEG1) { src = Wout; dh = woh;  dl = wol;  j = i - WSEG0; }
    else if (i < WSEG2) { src = W1;   dh = w1h;  dl = w1l;  j = i - WSEG1; }
    else                { src = W2;   dh = w2h;  dl = w2l;  j = i - WSEG2; }
    bf16 h, l; split_bf16(src[j], h, l); dh[j] = h; dl[j] = l;
}
// padded xproj weight: rows 152..191 zero
__global__ void wconv_pad_kernel(const float* __restrict__ W, bf16* __restrict__ wh,
                                 bf16* __restrict__ wl) {
    int i = blockIdx.x * 256 + threadIdx.x;
    if (i >= XDBP*768) return;
    int row = i / 768, col = i % 768;
    float v = (row < 152) ? W[row*768 + col] : 0.f;
    bf16 h, l; split_bf16(v, h, l); wh[i] = h; wl[i] = l;
}

// ---------------- LayerNorm -> bf16 hi/lo ----------------------------------
__global__ void ln_bf16_kernel(const float* __restrict__ x, const float* __restrict__ g,
                               const float* __restrict__ b, bf16* __restrict__ oh,
                               bf16* __restrict__ ol) {
    int row  = blockIdx.x * 8 + (threadIdx.x >> 5);
    int lane = threadIdx.x & 31;
    const float* xr = x + (size_t)row * DIMC;
    float v[12];
    float s = 0.f;
#pragma unroll
    for (int i = 0; i < 12; i++) { v[i] = xr[lane + 32*i]; s += v[i]; }
#pragma unroll
    for (int o = 16; o; o >>= 1) s += __shfl_xor_sync(~0u, s, o);
    float mu = s * (1.0f/DIMC);
    float q = 0.f;
#pragma unroll
    for (int i = 0; i < 12; i++) { float d = v[i]-mu; q += d*d; }
#pragma unroll
    for (int o = 16; o; o >>= 1) q += __shfl_xor_sync(~0u, q, o);
    float rs = rsqrtf(q*(1.0f/DIMC) + 1e-5f);
#pragma unroll
    for (int i = 0; i < 12; i++) {
        int c = lane + 32*i;
        float o = (v[i]-mu)*rs*g[c] + b[c];
        bf16 h, l; split_bf16(o, h, l);
        oh[(size_t)row*DIMC + c] = h;
        ol[(size_t)row*DIMC + c] = l;
    }
}

// =====================================================================
// bf16 split GEMM: C[M,N] = (Ah+Al)[M,K] @ (Bh+Bl)[N,K]^T (3-pass),
// cp.async double-buffered. BM=128, BN=64, BK=32. 256 thr = 8 warps (2x4).
// EPI: bit0 = +bias[col], bit1 = +res[row*N+col]
// =====================================================================
#define AST 40          // smem row stride in halves (80B)
#define STG 15360       // halves per stage
#define SM_BYTES (2*STG*2)

__device__ __forceinline__ void cp16(uint32_t dst, const void* src) {
    asm volatile("cp.async.cg.shared.global [%0], [%1], 16;" :: "r"(dst), "l"(src));
}
__device__ __forceinline__ void ldsm4(uint32_t r[4], uint32_t addr) {
    asm volatile("ldmatrix.sync.aligned.m8n8.x4.shared.b16 {%0,%1,%2,%3}, [%4];"
        : "=r"(r[0]), "=r"(r[1]), "=r"(r[2]), "=r"(r[3]) : "r"(addr));
}
__device__ __forceinline__ void mma16816(float c[4], const uint32_t a[4],
                                         uint32_t b0, uint32_t b1) {
    asm volatile("mma.sync.aligned.m16n8k16.row.col.f32.bf16.bf16.f32 "
        "{%0,%1,%2,%3}, {%4,%5,%6,%7}, {%8,%9}, {%0,%1,%2,%3};"
        : "+f"(c[0]), "+f"(c[1]), "+f"(c[2]), "+f"(c[3])
        : "r"(a[0]), "r"(a[1]), "r"(a[2]), "r"(a[3]), "r"(b0), "r"(b1));
}

template<int EPI>
__global__ void __launch_bounds__(256, 2)
bgemm_kernel(const bf16* __restrict__ Ah, const bf16* __restrict__ Al,
             const bf16* __restrict__ Bh, const bf16* __restrict__ Bl,
             float* __restrict__ C, const float* __restrict__ bias,
             const float* __restrict__ res, int M, int N, int K) {
    extern __shared__ bf16 sm[];
    const uint32_t base = (uint32_t)__cvta_generic_to_shared(sm);

    const int tid  = threadIdx.x;
    const int lane = tid & 31, warp = tid >> 5;
    const int wm = warp >> 2, wn = warp & 3;
    const int m0 = blockIdx.y * 128;
    const int n0 = blockIdx.x * 64;

    float acc[4][2][4];
#pragma unroll
    for (int i = 0; i < 4; i++)
#pragma unroll
        for (int j = 0; j < 2; j++)
#pragma unroll
            for (int t = 0; t < 4; t++) acc[i][j][t] = 0.f;

    const int iters = K / 32;

    const int ra0 = (tid*2) >> 2,  ka0 = (tid*2) & 3;
    const int ra1 = (tid*2+1) >> 2, ka1 = (tid*2+1) & 3;
    const int rb  = tid >> 2,       kb  = tid & 3;

    auto issue = [&](int it, int s) {
        const int k0 = it * 32;
        uint32_t sb = base + (uint32_t)(s*STG)*2;
        cp16(sb + (ra0*AST + ka0*8)*2,        Ah + (size_t)(m0+ra0)*K + k0 + ka0*8);
        cp16(sb + (ra1*AST + ka1*8)*2,        Ah + (size_t)(m0+ra1)*K + k0 + ka1*8);
        cp16(sb + (5120 + ra0*AST + ka0*8)*2, Al + (size_t)(m0+ra0)*K + k0 + ka0*8);
        cp16(sb + (5120 + ra1*AST + ka1*8)*2, Al + (size_t)(m0+ra1)*K + k0 + ka1*8);
        cp16(sb + (10240 + rb*AST + kb*8)*2,  Bh + (size_t)(n0+rb)*K + k0 + kb*8);
        cp16(sb + (12800 + rb*AST + kb*8)*2,  Bl + (size_t)(n0+rb)*K + k0 + kb*8);
        asm volatile("cp.async.commit_group;");
    };

    issue(0, 0);

    for (int it = 0; it < iters; ++it) {
        if (it + 1 < iters) {
            issue(it + 1, (it + 1) & 1);
            asm volatile("cp.async.wait_group 1;");
        } else {
            asm volatile("cp.async.wait_group 0;");
        }
        __syncthreads();

        const int s = it & 1;
        const uint32_t bAh = base + (uint32_t)(s*STG)*2;
        const uint32_t bAl = bAh + 5120*2;
        const uint32_t bBh = bAh + 10240*2;
        const uint32_t bBl = bAh + 12800*2;

#pragma unroll
        for (int st = 0; st < 2; st++) {
            const int kk = st * 16;
            uint32_t Ahf[4][4], Alf[4][4], Bhf[4], Blf[4];
            const int arow = (lane & 15);
            const int acol = kk + ((lane >> 4) * 8);
#pragma unroll
            for (int mf = 0; mf < 4; mf++) {
                uint32_t off = (uint32_t)((wm*64 + mf*16 + arow) * AST + acol) * 2;
                ldsm4(Ahf[mf], bAh + off);
                ldsm4(Alf[mf], bAl + off);
            }
            {
                const int brow = wn*16 + (lane & 7) + ((lane >> 4) * 8);
                const int bcol = kk + (((lane >> 3) & 1) * 8);
                uint32_t off = (uint32_t)(brow * AST + bcol) * 2;
                ldsm4(Bhf, bBh + off);
                ldsm4(Blf, bBl + off);
            }
#pragma unroll
            for (int mf = 0; mf < 4; mf++) {
                mma16816(acc[mf][0], Ahf[mf], Bhf[0], Bhf[1]);
                mma16816(acc[mf][1], Ahf[mf], Bhf[2], Bhf[3]);
                mma16816(acc[mf][0], Ahf[mf], Blf[0], Blf[1]);
                mma16816(acc[mf][1], Ahf[mf], Blf[2], Blf[3]);
                mma16816(acc[mf][0], Alf[mf], Bhf[0], Bhf[1]);
                mma16816(acc[mf][1], Alf[mf], Bhf[2], Bhf[3]);
            }
        }
        __syncthreads();
    }

    const int g = lane >> 2, tc = lane & 3;
#pragma unroll
    for (int mf = 0; mf < 4; mf++) {
#pragma unroll
        for (int nf = 0; nf < 2; nf++) {
            int col = n0 + wn*16 + nf*8 + tc*2;
            float b0 = 0.f, b1 = 0.f;
            if (EPI & 1) { b0 = bias[col]; b1 = bias[col+1]; }
#pragma unroll
            for (int half = 0; half < 2; half++) {
                int row = m0 + wm*64 + mf*16 + g + half*8;
                float v0 = acc[mf][nf][half*2]   + b0;
                float v1 = acc[mf][nf][half*2+1] + b1;
                if (EPI & 2) {
                    const float2 r = *(const float2*)(res + (size_t)row*N + col);
                    v0 += r.x; v1 += r.y;
                }
                *(float2*)(C + (size_t)row*N + col) = make_float2(v0, v1);
            }
        }
    }
}

// ---------------- causal depthwise conv1d (width 4) + SiLU, 4 t per thread --
__global__ void conv_silu_kernel(const float* __restrict__ xz, const float* __restrict__ cw,
                                 const float* __restrict__ cb, float* __restrict__ xc,
                                 bf16* __restrict__ xch, bf16* __restrict__ xcl) {
    int idx = blockIdx.x * 256 + threadIdx.x;      // over MROWS/4 * DIN
    int d   = idx % DIN;
    int tb  = idx / DIN;
    int b   = tb / (LTOK/4);
    int t0  = (tb % (LTOK/4)) * 4;
    const size_t rb0 = (size_t)b * LTOK;

    float w0 = cw[d*4+0], w1 = cw[d*4+1], w2 = cw[d*4+2], w3 = cw[d*4+3];
    float bias = cb[d];

    // inputs t0-3 .. t0+3 (7 values), zero before t=0
    float xin[7];
#pragma unroll
    for (int k = 0; k < 7; k++) {
        int tt = t0 + k - 3;
        xin[k] = (tt >= 0) ? xz[(rb0 + tt)*1536 + d] : 0.f;
    }
#pragma unroll
    for (int j = 0; j < 4; j++) {
        float acc = bias + xin[j]*w0 + xin[j+1]*w1 + xin[j+2]*w2 + xin[j+3]*w3;
        float s = acc / (1.f + __expf(-acc));
        size_t o = (rb0 + t0 + j)*DIN + d;
        xc[o] = s;
        bf16 h, l; split_bf16(s, h, l);
        xch[o] = h; xcl[o] = l;
    }
}

// ---------------- fused dt + selective scan ---------------------------------
#define SCH 8
#define STT 32
__global__ void __launch_bounds__(256)
scan_kernel(const float* __restrict__ xc, const float* __restrict__ xz,
            const float* __restrict__ xdb,
            const float* __restrict__ Wdt, const float* __restrict__ bdt,
            const float* __restrict__ A_log, const float* __restrict__ Dp,
            bf16* __restrict__ yh, bf16* __restrict__ yl) {
    __shared__ float s_xdb[STT][161];
    __shared__ float s_dt[STT][SCH];
    __shared__ float s_x [STT][SCH];
    __shared__ float s_z [STT][SCH];
    __shared__ float s_w [SCH][24];

    const int tid  = threadIdx.x;
    const int warp = tid >> 5, lane = tid & 31;
    const int b  = blockIdx.x / (DIN/SCH);
    const int d0 = (blockIdx.x % (DIN/SCH)) * SCH;
    const int d  = d0 + warp;

    if (tid < SCH*24) s_w[tid/24][tid%24] = Wdt[(d0 + tid/24)*24 + (tid%24)];
    const float bdt_c = bdt[d];
    const float A1 = -expf(A_log[d*DSTATE + lane]);
    const float A2 = -expf(A_log[d*DSTATE + lane + 32]);
    const float Dpd = Dp[d];
    float h1 = 0.f, h2 = 0.f;
    const size_t rbase = (size_t)b * LTOK;

    for (int t0 = 0; t0 < LTOK; t0 += STT) {
        __syncthreads();
        for (int i = tid; i < STT*40; i += 256) {
            int row = i / 40, q = i % 40;
            float4 v = *(const float4*)(xdb + (rbase + t0 + row)*XDBP + q*4);
            s_xdb[row][q*4+0] = v.x;
            s_xdb[row][q*4+1] = v.y;
            s_xdb[row][q*4+2] = v.z;
            s_xdb[row][q*4+3] = v.w;
        }
        if (tid < 64) {
            int row = tid >> 1, q = tid & 1;
            *(float4*)&s_x[row][q*4] =
                *(const float4*)(xc + (rbase + t0 + row)*DIN + d0 + q*4);
        } else if (tid < 128) {
            int i = tid - 64, row = i >> 1, q = i & 1;
            *(float4*)&s_z[row][q*4] =
                *(const float4*)(xz + (rbase + t0 + row)*1536 + DIN + d0 + q*4);
        }
        __syncthreads();
        {
            float acc = bdt_c;
#pragma unroll
            for (int k = 0; k < 24; k++) acc = fmaf(s_xdb[lane][k], s_w[warp][k], acc);
            s_dt[lane][warp] = (acc > 20.f) ? acc : log1pf(__expf(acc));
        }
        __syncthreads();
        for (int tt = 0; tt < STT; tt++) {
            float dtv = s_dt[tt][warp];
            float xv  = s_x[tt][warp];
            float B1 = s_xdb[tt][24+lane], B2 = s_xdb[tt][56+lane];
            float C1 = s_xdb[tt][88+lane], C2 = s_xdb[tt][120+lane];
            float dA1 = __expf(dtv*A1), dA2 = __expf(dtv*A2);
            float dtx = dtv * xv;
            h1 = h1*dA1 + dtx*B1;
            h2 = h2*dA2 + dtx*B2;
            float p = h1*C1 + h2*C2;
#pragma unroll
            for (int o = 16; o; o >>= 1) p += __shfl_xor_sync(~0u, p, o);
            if (lane == 0) {
                float zv = s_z[tt][warp];
                float yv = (p + xv*Dpd) * (zv / (1.f + __expf(-zv)));
                bf16 hh, ll; split_bf16(yv, hh, ll);
                size_t r = rbase + t0 + tt;
                yh[r*DIN + d] = hh; yl[r*DIN + d] = ll;
            }
        }
    }
}

// ---------------- 3x3 depthwise conv + exact GELU, 4 r per thread -----------
__global__ void dwconv_gelu_kernel(const float* __restrict__ f, const float* __restrict__ w,
                                   const float* __restrict__ bias,
                                   bf16* __restrict__ oh, bf16* __restrict__ ol) {
    int idx = blockIdx.x * 256 + threadIdx.x;      // over B*16*64*HIDC
    int d    = idx % HIDC;
    int rest = idx / HIDC;
    int c    = rest % 64;
    int rb   = (rest / 64) % 16;
    int b    = rest / (64*16);
    int r0   = rb * 4;

    float wv[9];
#pragma unroll
    for (int i = 0; i < 9; i++) wv[i] = w[d*9 + i];
    float bv = bias[d];

    const size_t base = (size_t)b * LTOK;
    // input rows r0-1 .. r0+4 (6 rows) x cols c-1..c+1
    float vin[6][3];
#pragma unroll
    for (int i = 0; i < 6; i++) {
        int rr = r0 + i - 1;
        bool rok = (unsigned)rr < 64u;
#pragma unroll
        for (int j = 0; j < 3; j++) {
            int cc = c + j - 1;
            vin[i][j] = (rok && (unsigned)cc < 64u)
                ? f[(base + rr*64 + cc)*HIDC + d] : 0.f;
        }
    }
#pragma unroll
    for (int jr = 0; jr < 4; jr++) {
        float acc = bv;
#pragma unroll
        for (int i = 0; i < 3; i++)
#pragma unroll
            for (int j = 0; j < 3; j++)
                acc = fmaf(vin[jr+i][j], wv[i*3+j], acc);
        float g = 0.5f * acc * (1.f + erff(acc * 0.7071067811865476f));
        bf16 h, l; split_bf16(g, h, l);
        size_t o = (base + (r0+jr)*64 + c)*HIDC + d;
        oh[o] = h; ol[o] = l;
    }
}

// ---------------- launch --------------------------------------------------
extern "C" void kernel_launch(void* const* d_in, const int* in_sizes, int n_in,
                              void* d_out, int out_size) {
    const float* x      = (const float*)d_in[0];
    const float* gamma1 = (const float*)d_in[3];
    const float* beta1  = (const float*)d_in[4];
    const float* W_in   = (const float*)d_in[5];
    const float* conv_w = (const float*)d_in[6];
    const float* conv_b = (const float*)d_in[7];
    const float* W_xprj = (const float*)d_in[8];
    const float* W_dt   = (const float*)d_in[9];
    const float* b_dt   = (const float*)d_in[10];
    const float* A_log  = (const float*)d_in[11];
    const float* Dp     = (const float*)d_in[12];
    const float* W_out  = (const float*)d_in[13];
    const float* gamma2 = (const float*)d_in[14];
    const float* beta2  = (const float*)d_in[15];
    const float* W1     = (const float*)d_in[16];
    const float* b1     = (const float*)d_in[17];
    const float* dw_w   = (const float*)d_in[18];
    const float* dw_b   = (const float*)d_in[19];
    const float* W2     = (const float*)d_in[20];
    const float* b2     = (const float*)d_in[21];

    float *xz, *xc, *xdb, *x2, *f1;
    bf16 *xnh, *xnl, *xch, *xcl, *yh, *yl, *f2h, *f2l;
    bf16 *winh, *winl, *wxh, *wxl, *woh, *wol, *w1h, *w1l, *w2h, *w2l;
    cudaGetSymbolAddress((void**)&xz,  g_xz);
    cudaGetSymbolAddress((void**)&xc,  g_xc);
    cudaGetSymbolAddress((void**)&xdb, g_xdb);
    cudaGetSymbolAddress((void**)&x2,  g_x2);
    cudaGetSymbolAddress((void**)&f1,  g_f1);
    cudaGetSymbolAddress((void**)&xnh, g_xnh);
    cudaGetSymbolAddress((void**)&xnl, g_xnl);
    cudaGetSymbolAddress((void**)&xch, g_xch);
    cudaGetSymbolAddress((void**)&xcl, g_xcl);
    cudaGetSymbolAddress((void**)&yh,  g_yh);
    cudaGetSymbolAddress((void**)&yl,  g_yl);
    cudaGetSymbolAddress((void**)&f2h, g_f2h);
    cudaGetSymbolAddress((void**)&f2l, g_f2l);
    cudaGetSymbolAddress((void**)&winh, g_winh);
    cudaGetSymbolAddress((void**)&winl, g_winl);
    cudaGetSymbolAddress((void**)&wxh,  g_wxh);
    cudaGetSymbolAddress((void**)&wxl,  g_wxl);
    cudaGetSymbolAddress((void**)&woh,  g_woh);
    cudaGetSymbolAddress((void**)&wol,  g_wol);
    cudaGetSymbolAddress((void**)&w1h,  g_w1h);
    cudaGetSymbolAddress((void**)&w1l,  g_w1l);
    cudaGetSymbolAddress((void**)&w2h,  g_w2h);
    cudaGetSymbolAddress((void**)&w2l,  g_w2l);

    cudaFuncSetAttribute(bgemm_kernel<0>, cudaFuncAttributeMaxDynamicSharedMemorySize, SM_BYTES);
    cudaFuncSetAttribute(bgemm_kernel<1>, cudaFuncAttributeMaxDynamicSharedMemorySize, SM_BYTES);
    cudaFuncSetAttribute(bgemm_kernel<2>, cudaFuncAttributeMaxDynamicSharedMemorySize, SM_BYTES);
    cudaFuncSetAttribute(bgemm_kernel<3>, cudaFuncAttributeMaxDynamicSharedMemorySize, SM_BYTES);

    // 0) all dense weight conversions
    wconv_all_kernel<<<(WTOT+255)/256, 256>>>(W_in, winh, winl, W_out, woh, wol,
                                              W1, w1h, w1l, W2, w2h, w2l);
    // 1) padded xproj weight
    wconv_pad_kernel<<<(XDBP*768+255)/256, 256>>>(W_xprj, wxh, wxl);
    // 2) LN1 -> bf16 hi/lo
    ln_bf16_kernel<<<MROWS/8, 256>>>(x, gamma1, beta1, xnh, xnl);
    // 3) xz = xn @ W_in^T  (N=1536, K=384)   <-- profiled instance (index 3)
    { dim3 g(1536/64, MROWS/128);
      bgemm_kernel<0><<<g, 256, SM_BYTES>>>(xnh, xnl, winh, winl, xz, nullptr, nullptr, MROWS, 1536, DIMC); }
    // 4) xc = silu(conv1d(xr)) (+ bf16 copies), 4 t per thread
    conv_silu_kernel<<<(MROWS/4*DIN)/256, 256>>>(xz, conv_w, conv_b, xc, xch, xcl);
    // 5) xdb = xc @ W_xproj^T  (N=192 padded, K=768)
    { dim3 g(XDBP/64, MROWS/128);
      bgemm_kernel<0><<<g, 256, SM_BYTES>>>(xch, xcl, wxh, wxl, xdb, nullptr, nullptr, MROWS, XDBP, DIN); }
    // 6) fused dt + scan -> y (bf16 hi/lo)
    scan_kernel<<<BATCH*(DIN/SCH), 256>>>(xc, xz, xdb, W_dt, b_dt, A_log, Dp, yh, yl);
    // 7) x2 = x + y @ W_out^T  (N=384, K=768)
    { dim3 g(DIMC/64, MROWS/128);
      bgemm_kernel<2><<<g, 256, SM_BYTES>>>(yh, yl, woh, wol, x2, nullptr, x, MROWS, DIMC, DIN); }
    // 8) LN2 -> bf16 hi/lo
    ln_bf16_kernel<<<MROWS/8, 256>>>(x2, gamma2, beta2, xnh, xnl);
    // 9) f1 = xn2 @ W1^T + b1  (N=1536, K=384)
    { dim3 g(HIDC/64, MROWS/128);
      bgemm_kernel<1><<<g, 256, SM_BYTES>>>(xnh, xnl, w1h, w1l, f1, b1, nullptr, MROWS, HIDC, DIMC); }
    // 10) f2 = gelu(dwconv3x3(f1)) (bf16 hi/lo), 4 r per thread
    dwconv_gelu_kernel<<<(MROWS/4*HIDC)/256, 256>>>(f1, dw_w, dw_b, f2h, f2l);
    // 11) out = x2 + f2 @ W2^T + b2  (N=384, K=1536)
    { dim3 g(DIMC/64, MROWS/128);
      bgemm_kernel<3><<<g, 256, SM_BYTES>>>(f2h, f2l, w2h, w2l, (float*)d_out, b2, x2, MROWS, DIMC, HIDC); }
}

// round 11
// speedup vs baseline: 1.5520x; 1.5520x over previous
#include <cuda_runtime.h>
#include <cuda_bf16.h>
#include <cstdint>

#define BATCH  8
#define LTOK   4096
#define DIMC   384
#define DIN    768
#define DSTATE 64
#define DTRANK 24
#define HIDC   1536
#define MROWS  (BATCH*LTOK)   // 32768
#define XDBP   192            // padded xproj width (152 -> 192)

typedef __nv_bfloat16 bf16;

// ---------------- scratch (static device memory) ---------------------------
__device__ float g_xz [ (size_t)MROWS*1536 ];
__device__ float g_xc [ (size_t)MROWS*DIN  ];
__device__ float g_xdb[ (size_t)MROWS*XDBP ];
__device__ float g_x2 [ (size_t)MROWS*DIMC ];
__device__ float g_f1 [ (size_t)MROWS*HIDC ];

__device__ alignas(16) bf16 g_xnh[ (size_t)MROWS*DIMC ];
__device__ alignas(16) bf16 g_xnl[ (size_t)MROWS*DIMC ];
__device__ alignas(16) bf16 g_xch[ (size_t)MROWS*DIN  ];
__device__ alignas(16) bf16 g_xcl[ (size_t)MROWS*DIN  ];
__device__ alignas(16) bf16 g_yh [ (size_t)MROWS*DIN  ];
__device__ alignas(16) bf16 g_yl [ (size_t)MROWS*DIN  ];
__device__ alignas(16) bf16 g_f2h[ (size_t)MROWS*HIDC ];
__device__ alignas(16) bf16 g_f2l[ (size_t)MROWS*HIDC ];

// weights hi/lo
__device__ alignas(16) bf16 g_winh[1536*384], g_winl[1536*384];
__device__ alignas(16) bf16 g_wxh [XDBP*768], g_wxl [XDBP*768];
__device__ alignas(16) bf16 g_woh [384*768],  g_wol [384*768];
__device__ alignas(16) bf16 g_w1h [1536*384], g_w1l [1536*384];
__device__ alignas(16) bf16 g_w2h [384*1536], g_w2l [384*1536];

__device__ __forceinline__ void split_bf16(float v, bf16& h, bf16& l) {
    h = __float2bfloat16(v);
    l = __float2bfloat16(v - __bfloat162float(h));
}

// ---------------- ALL dense weight conversions in ONE launch ----------------
#define WSEG0 589824
#define WSEG1 (WSEG0 + 294912)   // 884736
#define WSEG2 (WSEG1 + 589824)   // 1474560
#define WTOT  (WSEG2 + 589824)   // 2064384
__global__ void wconv_all_kernel(const float* __restrict__ Win,  bf16* winh, bf16* winl,
                                 const float* __restrict__ Wout, bf16* woh,  bf16* wol,
                                 const float* __restrict__ W1,   bf16* w1h,  bf16* w1l,
                                 const float* __restrict__ W2,   bf16* w2h,  bf16* w2l) {
    int i = blockIdx.x * 256 + threadIdx.x;
    if (i >= WTOT) return;
    const float* src; bf16 *dh, *dl; int j;
    if (i < WSEG0)      { src = Win;  dh = winh; dl = winl; j = i; }
    else if (i < WSEG1) { src = Wout; dh = woh;  dl = wol;  j = i - WSEG0; }
    else if (i < WSEG2) { src = W1;   dh = w1h;  dl = w1l;  j = i - WSEG1; }
    else                { src = W2;   dh = w2h;  dl = w2l;  j = i - WSEG2; }
    bf16 h, l; split_bf16(src[j], h, l); dh[j] = h; dl[j] = l;
}
// padded xproj weight: rows 152..191 zero
__global__ void wconv_pad_kernel(const float* __restrict__ W, bf16* __restrict__ wh,
                                 bf16* __restrict__ wl) {
    int i = blockIdx.x * 256 + threadIdx.x;
    if (i >= XDBP*768) return;
    int row = i / 768, col = i % 768;
    float v = (row < 152) ? W[row*768 + col] : 0.f;
    bf16 h, l; split_bf16(v, h, l); wh[i] = h; wl[i] = l;
}

// ---------------- LayerNorm -> bf16 hi/lo ----------------------------------
__global__ void ln_bf16_kernel(const float* __restrict__ x, const float* __restrict__ g,
                               const float* __restrict__ b, bf16* __restrict__ oh,
                               bf16* __restrict__ ol) {
    int row  = blockIdx.x * 8 + (threadIdx.x >> 5);
    int lane = threadIdx.x & 31;
    const float* xr = x + (size_t)row * DIMC;
    float v[12];
    float s = 0.f;
#pragma unroll
    for (int i = 0; i < 12; i++) { v[i] = xr[lane + 32*i]; s += v[i]; }
#pragma unroll
    for (int o = 16; o; o >>= 1) s += __shfl_xor_sync(~0u, s, o);
    float mu = s * (1.0f/DIMC);
    float q = 0.f;
#pragma unroll
    for (int i = 0; i < 12; i++) { float d = v[i]-mu; q += d*d; }
#pragma unroll
    for (int o = 16; o; o >>= 1) q += __shfl_xor_sync(~0u, q, o);
    float rs = rsqrtf(q*(1.0f/DIMC) + 1e-5f);
#pragma unroll
    for (int i = 0; i < 12; i++) {
        int c = lane + 32*i;
        float o = (v[i]-mu)*rs*g[c] + b[c];
        bf16 h, l; split_bf16(o, h, l);
        oh[(size_t)row*DIMC + c] = h;
        ol[(size_t)row*DIMC + c] = l;
    }
}

// =====================================================================
// bf16 split GEMM: C[M,N] = (Ah+Al)[M,K] @ (Bh+Bl)[N,K]^T (3-pass),
// cp.async 3-stage pipeline, ONE __syncthreads per k-iteration.
// BM=128, BN=64, BK=32. 256 thr = 8 warps (2x4).
// EPI: bit0 = +bias[col], bit1 = +res[row*N+col]
// =====================================================================
#define AST 40          // smem row stride in halves (80B)
#define STG 15360       // halves per stage
#define NSTAGE 3
#define SM_BYTES (NSTAGE*STG*2)

__device__ __forceinline__ void cp16(uint32_t dst, const void* src) {
    asm volatile("cp.async.cg.shared.global [%0], [%1], 16;" :: "r"(dst), "l"(src));
}
__device__ __forceinline__ void ldsm4(uint32_t r[4], uint32_t addr) {
    asm volatile("ldmatrix.sync.aligned.m8n8.x4.shared.b16 {%0,%1,%2,%3}, [%4];"
        : "=r"(r[0]), "=r"(r[1]), "=r"(r[2]), "=r"(r[3]) : "r"(addr));
}
__device__ __forceinline__ void mma16816(float c[4], const uint32_t a[4],
                                         uint32_t b0, uint32_t b1) {
    asm volatile("mma.sync.aligned.m16n8k16.row.col.f32.bf16.bf16.f32 "
        "{%0,%1,%2,%3}, {%4,%5,%6,%7}, {%8,%9}, {%0,%1,%2,%3};"
        : "+f"(c[0]), "+f"(c[1]), "+f"(c[2]), "+f"(c[3])
        : "r"(a[0]), "r"(a[1]), "r"(a[2]), "r"(a[3]), "r"(b0), "r"(b1));
}

template<int EPI>
__global__ void __launch_bounds__(256, 2)
bgemm_kernel(const bf16* __restrict__ Ah, const bf16* __restrict__ Al,
             const bf16* __restrict__ Bh, const bf16* __restrict__ Bl,
             float* __restrict__ C, const float* __restrict__ bias,
             const float* __restrict__ res, int M, int N, int K) {
    extern __shared__ bf16 sm[];
    const uint32_t base = (uint32_t)__cvta_generic_to_shared(sm);

    const int tid  = threadIdx.x;
    const int lane = tid & 31, warp = tid >> 5;
    const int wm = warp >> 2, wn = warp & 3;
    const int m0 = blockIdx.y * 128;
    const int n0 = blockIdx.x * 64;

    float acc[4][2][4];
#pragma unroll
    for (int i = 0; i < 4; i++)
#pragma unroll
        for (int j = 0; j < 2; j++)
#pragma unroll
            for (int t = 0; t < 4; t++) acc[i][j][t] = 0.f;

    const int iters = K / 32;

    const int ra0 = (tid*2) >> 2,  ka0 = (tid*2) & 3;
    const int ra1 = (tid*2+1) >> 2, ka1 = (tid*2+1) & 3;
    const int rb  = tid >> 2,       kb  = tid & 3;

    auto issue = [&](int it) {
        const int k0 = it * 32;
        uint32_t sb = base + (uint32_t)((it % NSTAGE)*STG)*2;
        cp16(sb + (ra0*AST + ka0*8)*2,        Ah + (size_t)(m0+ra0)*K + k0 + ka0*8);
        cp16(sb + (ra1*AST + ka1*8)*2,        Ah + (size_t)(m0+ra1)*K + k0 + ka1*8);
        cp16(sb + (5120 + ra0*AST + ka0*8)*2, Al + (size_t)(m0+ra0)*K + k0 + ka0*8);
        cp16(sb + (5120 + ra1*AST + ka1*8)*2, Al + (size_t)(m0+ra1)*K + k0 + ka1*8);
        cp16(sb + (10240 + rb*AST + kb*8)*2,  Bh + (size_t)(n0+rb)*K + k0 + kb*8);
        cp16(sb + (12800 + rb*AST + kb*8)*2,  Bl + (size_t)(n0+rb)*K + k0 + kb*8);
        asm volatile("cp.async.commit_group;");
    };

    // prologue: stages 0,1 in flight
    issue(0);
    issue(1);

    for (int it = 0; it < iters; ++it) {
        // ensure stage `it` landed (allow the newest 1 group to still be in flight)
        if (it + 1 < iters) asm volatile("cp.async.wait_group 1;");
        else                asm volatile("cp.async.wait_group 0;");
        __syncthreads();
        // all warps are now past compute(it-1); buffer (it+2)%3 == (it-1)%3 is free
        if (it + 2 < iters) issue(it + 2);

        const uint32_t bAh = base + (uint32_t)((it % NSTAGE)*STG)*2;
        const uint32_t bAl = bAh + 5120*2;
        const uint32_t bBh = bAh + 10240*2;
        const uint32_t bBl = bAh + 12800*2;

#pragma unroll
        for (int st = 0; st < 2; st++) {
            const int kk = st * 16;
            uint32_t Ahf[4][4], Alf[4][4], Bhf[4], Blf[4];
            const int arow = (lane & 15);
            const int acol = kk + ((lane >> 4) * 8);
#pragma unroll
            for (int mf = 0; mf < 4; mf++) {
                uint32_t off = (uint32_t)((wm*64 + mf*16 + arow) * AST + acol) * 2;
                ldsm4(Ahf[mf], bAh + off);
                ldsm4(Alf[mf], bAl + off);
            }
            {
                const int brow = wn*16 + (lane & 7) + ((lane >> 4) * 8);
                const int bcol = kk + (((lane >> 3) & 1) * 8);
                uint32_t off = (uint32_t)(brow * AST + bcol) * 2;
                ldsm4(Bhf, bBh + off);
                ldsm4(Blf, bBl + off);
            }
#pragma unroll
            for (int mf = 0; mf < 4; mf++) {
                mma16816(acc[mf][0], Ahf[mf], Bhf[0], Bhf[1]);
                mma16816(acc[mf][1], Ahf[mf], Bhf[2], Bhf[3]);
                mma16816(acc[mf][0], Ahf[mf], Blf[0], Blf[1]);
                mma16816(acc[mf][1], Ahf[mf], Blf[2], Blf[3]);
                mma16816(acc[mf][0], Alf[mf], Bhf[0], Bhf[1]);
                mma16816(acc[mf][1], Alf[mf], Bhf[2], Bhf[3]);
            }
        }
    }

    const int g = lane >> 2, tc = lane & 3;
#pragma unroll
    for (int mf = 0; mf < 4; mf++) {
#pragma unroll
        for (int nf = 0; nf < 2; nf++) {
            int col = n0 + wn*16 + nf*8 + tc*2;
            float b0 = 0.f, b1 = 0.f;
            if (EPI & 1) { b0 = bias[col]; b1 = bias[col+1]; }
#pragma unroll
            for (int half = 0; half < 2; half++) {
                int row = m0 + wm*64 + mf*16 + g + half*8;
                float v0 = acc[mf][nf][half*2]   + b0;
                float v1 = acc[mf][nf][half*2+1] + b1;
                if (EPI & 2) {
                    const float2 r = *(const float2*)(res + (size_t)row*N + col);
                    v0 += r.x; v1 += r.y;
                }
                *(float2*)(C + (size_t)row*N + col) = make_float2(v0, v1);
            }
        }
    }
}

// ---------------- causal depthwise conv1d (width 4) + SiLU ------------------
// (round-9 version: one output per thread — the 4x blocked variant regressed)
__global__ void conv_silu_kernel(const float* __restrict__ xz, const float* __restrict__ cw,
                                 const float* __restrict__ cb, float* __restrict__ xc,
                                 bf16* __restrict__ xch, bf16* __restrict__ xcl) {
    int idx = blockIdx.x * 256 + threadIdx.x;
    int d   = idx % DIN;
    int row = idx / DIN;
    int t   = row % LTOK;
    float acc = cb[d];
#pragma unroll
    for (int k = 0; k < 4; k++) {
        int tt = t + k - 3;
        if (tt >= 0)
            acc += xz[(size_t)(row + k - 3)*1536 + d] * cw[d*4 + k];
    }
    float s = acc / (1.f + __expf(-acc));
    xc[idx] = s;
    bf16 h, l; split_bf16(s, h, l);
    xch[idx] = h; xcl[idx] = l;
}

// ---------------- fused dt + selective scan ---------------------------------
#define SCH 8
#define STT 32
__global__ void __launch_bounds__(256)
scan_kernel(const float* __restrict__ xc, const float* __restrict__ xz,
            const float* __restrict__ xdb,
            const float* __restrict__ Wdt, const float* __restrict__ bdt,
            const float* __restrict__ A_log, const float* __restrict__ Dp,
            bf16* __restrict__ yh, bf16* __restrict__ yl) {
    __shared__ float s_xdb[STT][161];
    __shared__ float s_dt[STT][SCH];
    __shared__ float s_x [STT][SCH];
    __shared__ float s_z [STT][SCH];
    __shared__ float s_w [SCH][24];

    const int tid  = threadIdx.x;
    const int warp = tid >> 5, lane = tid & 31;
    const int b  = blockIdx.x / (DIN/SCH);
    const int d0 = (blockIdx.x % (DIN/SCH)) * SCH;
    const int d  = d0 + warp;

    if (tid < SCH*24) s_w[tid/24][tid%24] = Wdt[(d0 + tid/24)*24 + (tid%24)];
    const float bdt_c = bdt[d];
    const float A1 = -expf(A_log[d*DSTATE + lane]);
    const float A2 = -expf(A_log[d*DSTATE + lane + 32]);
    const float Dpd = Dp[d];
    float h1 = 0.f, h2 = 0.f;
    const size_t rbase = (size_t)b * LTOK;

    for (int t0 = 0; t0 < LTOK; t0 += STT) {
        __syncthreads();
        for (int i = tid; i < STT*40; i += 256) {
            int row = i / 40, q = i % 40;
            float4 v = *(const float4*)(xdb + (rbase + t0 + row)*XDBP + q*4);
            s_xdb[row][q*4+0] = v.x;
            s_xdb[row][q*4+1] = v.y;
            s_xdb[row][q*4+2] = v.z;
            s_xdb[row][q*4+3] = v.w;
        }
        if (tid < 64) {
            int row = tid >> 1, q = tid & 1;
            *(float4*)&s_x[row][q*4] =
                *(const float4*)(xc + (rbase + t0 + row)*DIN + d0 + q*4);
        } else if (tid < 128) {
            int i = tid - 64, row = i >> 1, q = i & 1;
            *(float4*)&s_z[row][q*4] =
                *(const float4*)(xz + (rbase + t0 + row)*1536 + DIN + d0 + q*4);
        }
        __syncthreads();
        {
            float acc = bdt_c;
#pragma unroll
            for (int k = 0; k < 24; k++) acc = fmaf(s_xdb[lane][k], s_w[warp][k], acc);
            s_dt[lane][warp] = (acc > 20.f) ? acc : log1pf(__expf(acc));
        }
        __syncthreads();
        for (int tt = 0; tt < STT; tt++) {
            float dtv = s_dt[tt][warp];
            float xv  = s_x[tt][warp];
            float B1 = s_xdb[tt][24+lane], B2 = s_xdb[tt][56+lane];
            float C1 = s_xdb[tt][88+lane], C2 = s_xdb[tt][120+lane];
            float dA1 = __expf(dtv*A1), dA2 = __expf(dtv*A2);
            float dtx = dtv * xv;
            h1 = h1*dA1 + dtx*B1;
            h2 = h2*dA2 + dtx*B2;
            float p = h1*C1 + h2*C2;
#pragma unroll
            for (int o = 16; o; o >>= 1) p += __shfl_xor_sync(~0u, p, o);
            if (lane == 0) {
                float zv = s_z[tt][warp];
                float yv = (p + xv*Dpd) * (zv / (1.f + __expf(-zv)));
                bf16 hh, ll; split_bf16(yv, hh, ll);
                size_t r = rbase + t0 + tt;
                yh[r*DIN + d] = hh; yl[r*DIN + d] = ll;
            }
        }
    }
}

// ---------------- 3x3 depthwise conv on 64x64 grid + exact GELU -------------
// (round-9 version: one output per thread — the 4x blocked variant regressed)
__global__ void dwconv_gelu_kernel(const float* __restrict__ f, const float* __restrict__ w,
                                   const float* __restrict__ bias,
                                   bf16* __restrict__ oh, bf16* __restrict__ ol) {
    int idx = blockIdx.x * 256 + threadIdx.x;
    int d = idx % HIDC;
    int n = (idx / HIDC) % LTOK;
    int b = idx / (HIDC * LTOK);
    int r = n >> 6, c = n & 63;
    float acc = bias[d];
#pragma unroll
    for (int i = 0; i < 3; i++) {
        int rr = r + i - 1;
        if ((unsigned)rr < 64u) {
#pragma unroll
            for (int j = 0; j < 3; j++) {
                int cc = c + j - 1;
                if ((unsigned)cc < 64u)
                    acc += f[((size_t)b*LTOK + rr*64 + cc)*HIDC + d] * w[d*9 + i*3 + j];
            }
        }
    }
    float g = 0.5f * acc * (1.f + erff(acc * 0.7071067811865476f));
    bf16 h, l; split_bf16(g, h, l);
    oh[idx] = h; ol[idx] = l;
}

// ---------------- launch --------------------------------------------------
extern "C" void kernel_launch(void* const* d_in, const int* in_sizes, int n_in,
                              void* d_out, int out_size) {
    const float* x      = (const float*)d_in[0];
    const float* gamma1 = (const float*)d_in[3];
    const float* beta1  = (const float*)d_in[4];
    const float* W_in   = (const float*)d_in[5];
    const float* conv_w = (const float*)d_in[6];
    const float* conv_b = (const float*)d_in[7];
    const float* W_xprj = (const float*)d_in[8];
    const float* W_dt   = (const float*)d_in[9];
    const float* b_dt   = (const float*)d_in[10];
    const float* A_log  = (const float*)d_in[11];
    const float* Dp     = (const float*)d_in[12];
    const float* W_out  = (const float*)d_in[13];
    const float* gamma2 = (const float*)d_in[14];
    const float* beta2  = (const float*)d_in[15];
    const float* W1     = (const float*)d_in[16];
    const float* b1     = (const float*)d_in[17];
    const float* dw_w   = (const float*)d_in[18];
    const float* dw_b   = (const float*)d_in[19];
    const float* W2     = (const float*)d_in[20];
    const float* b2     = (const float*)d_in[21];

    float *xz, *xc, *xdb, *x2, *f1;
    bf16 *xnh, *xnl, *xch, *xcl, *yh, *yl, *f2h, *f2l;
    bf16 *winh, *winl, *wxh, *wxl, *woh, *wol, *w1h, *w1l, *w2h, *w2l;
    cudaGetSymbolAddress((void**)&xz,  g_xz);
    cudaGetSymbolAddress((void**)&xc,  g_xc);
    cudaGetSymbolAddress((void**)&xdb, g_xdb);
    cudaGetSymbolAddress((void**)&x2,  g_x2);
    cudaGetSymbolAddress((void**)&f1,  g_f1);
    cudaGetSymbolAddress((void**)&xnh, g_xnh);
    cudaGetSymbolAddress((void**)&xnl, g_xnl);
    cudaGetSymbolAddress((void**)&xch, g_xch);
    cudaGetSymbolAddress((void**)&xcl, g_xcl);
    cudaGetSymbolAddress((void**)&yh,  g_yh);
    cudaGetSymbolAddress((void**)&yl,  g_yl);
    cudaGetSymbolAddress((void**)&f2h, g_f2h);
    cudaGetSymbolAddress((void**)&f2l, g_f2l);
    cudaGetSymbolAddress((void**)&winh, g_winh);
    cudaGetSymbolAddress((void**)&winl, g_winl);
    cudaGetSymbolAddress((void**)&wxh,  g_wxh);
    cudaGetSymbolAddress((void**)&wxl,  g_wxl);
    cudaGetSymbolAddress((void**)&woh,  g_woh);
    cudaGetSymbolAddress((void**)&wol,  g_wol);
    cudaGetSymbolAddress((void**)&w1h,  g_w1h);
    cudaGetSymbolAddress((void**)&w1l,  g_w1l);
    cudaGetSymbolAddress((void**)&w2h,  g_w2h);
    cudaGetSymbolAddress((void**)&w2l,  g_w2l);

    cudaFuncSetAttribute(bgemm_kernel<0>, cudaFuncAttributeMaxDynamicSharedMemorySize, SM_BYTES);
    cudaFuncSetAttribute(bgemm_kernel<1>, cudaFuncAttributeMaxDynamicSharedMemorySize, SM_BYTES);
    cudaFuncSetAttribute(bgemm_kernel<2>, cudaFuncAttributeMaxDynamicSharedMemorySize, SM_BYTES);
    cudaFuncSetAttribute(bgemm_kernel<3>, cudaFuncAttributeMaxDynamicSharedMemorySize, SM_BYTES);

    // 0) all dense weight conversions
    wconv_all_kernel<<<(WTOT+255)/256, 256>>>(W_in, winh, winl, W_out, woh, wol,
                                              W1, w1h, w1l, W2, w2h, w2l);
    // 1) padded xproj weight
    wconv_pad_kernel<<<(XDBP*768+255)/256, 256>>>(W_xprj, wxh, wxl);
    // 2) LN1 -> bf16 hi/lo
    ln_bf16_kernel<<<MROWS/8, 256>>>(x, gamma1, beta1, xnh, xnl);
    // 3) xz = xn @ W_in^T  (N=1536, K=384)   <-- profiled instance (index 3)
    { dim3 g(1536/64, MROWS/128);
      bgemm_kernel<0><<<g, 256, SM_BYTES>>>(xnh, xnl, winh, winl, xz, nullptr, nullptr, MROWS, 1536, DIMC); }
    // 4) xc = silu(conv1d(xr)) (+ bf16 copies)
    conv_silu_kernel<<<(MROWS*DIN)/256, 256>>>(xz, conv_w, conv_b, xc, xch, xcl);
    // 5) xdb = xc @ W_xproj^T  (N=192 padded, K=768)
    { dim3 g(XDBP/64, MROWS/128);
      bgemm_kernel<0><<<g, 256, SM_BYTES>>>(xch, xcl, wxh, wxl, xdb, nullptr, nullptr, MROWS, XDBP, DIN); }
    // 6) fused dt + scan -> y (bf16 hi/lo)
    scan_kernel<<<BATCH*(DIN/SCH), 256>>>(xc, xz, xdb, W_dt, b_dt, A_log, Dp, yh, yl);
    // 7) x2 = x + y @ W_out^T  (N=384, K=768)
    { dim3 g(DIMC/64, MROWS/128);
      bgemm_kernel<2><<<g, 256, SM_BYTES>>>(yh, yl, woh, wol, x2, nullptr, x, MROWS, DIMC, DIN); }
    // 8) LN2 -> bf16 hi/lo
    ln_bf16_kernel<<<MROWS/8, 256>>>(x2, gamma2, beta2, xnh, xnl);
    // 9) f1 = xn2 @ W1^T + b1  (N=1536, K=384)
    { dim3 g(HIDC/64, MROWS/128);
      bgemm_kernel<1><<<g, 256, SM_BYTES>>>(xnh, xnl, w1h, w1l, f1, b1, nullptr, MROWS, HIDC, DIMC); }
    // 10) f2 = gelu(dwconv3x3(f1)) (bf16 hi/lo)
    dwconv_gelu_kernel<<<(MROWS*HIDC)/256, 256>>>(f1, dw_w, dw_b, f2h, f2l);
    // 11) out = x2 + f2 @ W2^T + b2  (N=384, K=1536)
    { dim3 g(DIMC/64, MROWS/128);
      bgemm_kernel<3><<<g, 256, SM_BYTES>>>(f2h, f2l, w2h, w2l, (float*)d_out, b2, x2, MROWS, DIMC, HIDC); }
}